// round 6
// baseline (speedup 1.0000x reference)
#include <cuda_runtime.h>
#include <cstdint>

// ---------------- problem constants ----------------
#define NPTS     16384          // 16 * 32 * 32 points
#define DIM      256            // embedding dim (channels)
#define KCODES   8192           // codebook size
#define XSTRIDE_B 262144        // 256 * 1024 floats per batch in x layout
#define SPATIAL  1024           // 32*32

// output packing (tuple order, flattened):
// quantized_st [4194304] | loss [1] | perplexity [1] |
// new_embedding [2097152] | new_cluster_size [8192] | new_embed_avg [2097152]
#define LOSS_OFF 4194304u
#define PPL_OFF  4194305u
#define EMB_OFF  4194306u
#define CS_OFF   6291458u
#define EAVG_OFF 6299650u

// ---------------- scratch (no allocations allowed) ----------------
__device__ int   g_idx[NPTS];
__device__ float g_count[KCODES];
__device__ float g_dw[KCODES * DIM];
__device__ float g_cnorm[KCODES];
__device__ float g_xnorm[NPTS];
__device__ float g_loss;

// ---------------- kernel 0: zero scratch (graph-replay safe) ----------------
__global__ void k_zero() {
    int i = blockIdx.x * blockDim.x + threadIdx.x;   // grid covers KCODES*DIM
    g_dw[i] = 0.f;
    if (i < KCODES) g_count[i] = 0.f;
    if (i == 0) g_loss = 0.f;
}

// ---------------- kernel 1: code norms ||e_k||^2 ----------------
__global__ void k_cnorm(const float* __restrict__ emb) {
    int w = (blockIdx.x * blockDim.x + threadIdx.x) >> 5;   // one warp per code
    int lane = threadIdx.x & 31;
    if (w >= KCODES) return;
    const float4* r = reinterpret_cast<const float4*>(emb + (size_t)w * DIM);
    float s = 0.f;
#pragma unroll
    for (int q = 0; q < 2; q++) {
        float4 v = r[lane + 32 * q];
        s += v.x * v.x + v.y * v.y + v.z * v.z + v.w * v.w;
    }
#pragma unroll
    for (int off = 16; off; off >>= 1) s += __shfl_xor_sync(0xffffffffu, s, off);
    if (lane == 0) g_cnorm[w] = s;
}

// ---------------- kernel 1b: point norms A_n = ||x_n||^2 (near-exact) -------
// Needed to EMULATE the reference's fp32 score  s = fl(fl(A - 2*dot) + C),
// whose dominant rounding happens at magnitude ~256. Double accumulation gives
// A correct to <=0.5 ulp, so the emulated roundings match the reference's.
__global__ void k_xnorm(const float* __restrict__ x) {
    int n = blockIdx.x * 256 + threadIdx.x;        // 0..16383
    int b = n >> 10, s = n & 1023;
    const float* xb = x + (size_t)b * XSTRIDE_B + s;
    double acc = 0.0;
#pragma unroll 8
    for (int d = 0; d < DIM; d++) {
        float v = xb[(size_t)d * SPATIAL];
        acc += (double)v * (double)v;
    }
    g_xnorm[n] = (float)acc;
}

// ---------------- kernel 2: fused fp32x2 GEMM + row argmin ----------------
// score emulates reference bitwise-structure: s = fl(fl(A - 2*dot) + ||e||^2).
// The magnitude-256 quantization turns near-ties into exact fp32 ties, which
// first-index tiebreak then resolves identically to jnp.argmin.
// Block tile: 64 points x 128 codes, K streamed in DK=16 chunks, double-buffered.
// Thread tile: 4 points x 8 codes (4 f32x2 pairs). x stored DUPLICATED in smem
// ({x,x} pairs) so the broadcast operand comes packed from LDS.128 -> no MOVs.
#define MT 64
#define NT 128
#define DK 16
#define NCHUNK (DIM / DK)        // 16
#define NTILES (KCODES / NT)     // 64
#define TOTCH  (NTILES * NCHUNK) // 1024

__global__ __launch_bounds__(256, 2)
void k_argmin(const float* __restrict__ x, const float* __restrict__ emb) {
    __shared__ float sx[2][DK][2 * MT];   // duplicated x: [d][2p],[2p+1] = x[p][d]
    __shared__ float se[2][DK][NT];       // e transposed:  [d][c]

    const int tid = threadIdx.x;
    const int i = tid >> 4;               // 0..15 point group (4 pts each)
    const int j = tid & 15;               // 0..15 code group (8 codes each)

    const int n0 = blockIdx.x * MT;
    const int b  = n0 >> 10;
    const int s0 = n0 & 1023;
    const float* xb = x + (size_t)b * XSTRIDE_B + s0;

    // loader roles
    const int ld_d = tid >> 4;            // 0..15 : within-chunk d for x load
    const int ld_p = (tid & 15) << 2;     // 0..60 : 4 consecutive points
    const int le_c = tid >> 1;            // 0..127: code row for e load
    const int le_h = tid & 1;             // which 8 of the 16 d's

    float4 rx, re0, re1;

    // prefetch chunk 0 (tile 0, d0 = 0)
    rx = *reinterpret_cast<const float4*>(xb + (size_t)ld_d * SPATIAL + ld_p);
    {
        const float* ep = emb + (size_t)le_c * DIM + le_h * 8;
        re0 = *reinterpret_cast<const float4*>(ep);
        re1 = *reinterpret_cast<const float4*>(ep + 4);
    }

    const float INF = __int_as_float(0x7f800000);
    float run_v[4] = {INF, INF, INF, INF};
    int   run_k[4] = {0, 0, 0, 0};

    // per-point A = ||x||^2 (constant across tiles)
    float Ap[4];
#pragma unroll
    for (int p = 0; p < 4; p++) Ap[p] = g_xnorm[n0 + 4 * i + p];

    // store chunk 0 into buffer 0
    {
        float2* dx = reinterpret_cast<float2*>(&sx[0][ld_d][2 * ld_p]);
        dx[0] = make_float2(rx.x, rx.x);
        dx[1] = make_float2(rx.y, rx.y);
        dx[2] = make_float2(rx.z, rx.z);
        dx[3] = make_float2(rx.w, rx.w);
        int dd = le_h * 8;
        se[0][dd + 0][le_c] = re0.x; se[0][dd + 1][le_c] = re0.y;
        se[0][dd + 2][le_c] = re0.z; se[0][dd + 3][le_c] = re0.w;
        se[0][dd + 4][le_c] = re1.x; se[0][dd + 5][le_c] = re1.y;
        se[0][dd + 6][le_c] = re1.z; se[0][dd + 7][le_c] = re1.w;
    }
    __syncthreads();

#pragma unroll 1
    for (int t = 0; t < NTILES; t++) {
        unsigned long long acc[4][4];
#pragma unroll
        for (int p = 0; p < 4; p++)
#pragma unroll
            for (int c = 0; c < 4; c++) acc[p][c] = 0ull;

#pragma unroll 1
        for (int kc = 0; kc < NCHUNK; kc++) {
            const int cur = (t * NCHUNK + kc) & 1;
            const int nc  = t * NCHUNK + kc + 1;
            const bool more = (nc < TOTCH);
            if (more) {
                const int k0 = (nc >> 4) * NT;
                const int d0 = (nc & 15) * DK;
                rx = *reinterpret_cast<const float4*>(
                        xb + (size_t)(d0 + ld_d) * SPATIAL + ld_p);
                const float* ep = emb + (size_t)(k0 + le_c) * DIM + d0 + le_h * 8;
                re0 = *reinterpret_cast<const float4*>(ep);
                re1 = *reinterpret_cast<const float4*>(ep + 4);
            }

            // compute current chunk: 16 d * 16 FFMA2 per thread
#pragma unroll
            for (int d = 0; d < DK; d++) {
                const ulonglong2* ap =
                    reinterpret_cast<const ulonglong2*>(&sx[cur][d][8 * i]);
                ulonglong2 a01 = ap[0], a23 = ap[1];
                const ulonglong2* bp =
                    reinterpret_cast<const ulonglong2*>(&se[cur][d][8 * j]);
                ulonglong2 b01 = bp[0], b23 = bp[1];
                unsigned long long av[4] = {a01.x, a01.y, a23.x, a23.y};
                unsigned long long bv[4] = {b01.x, b01.y, b23.x, b23.y};
#pragma unroll
                for (int p = 0; p < 4; p++)
#pragma unroll
                    for (int c = 0; c < 4; c++)
                        asm("fma.rn.f32x2 %0, %1, %2, %0;"
                            : "+l"(acc[p][c]) : "l"(av[p]), "l"(bv[c]));
            }

            if (more) {
                const int nxt = nc & 1;
                float2* dx = reinterpret_cast<float2*>(&sx[nxt][ld_d][2 * ld_p]);
                dx[0] = make_float2(rx.x, rx.x);
                dx[1] = make_float2(rx.y, rx.y);
                dx[2] = make_float2(rx.z, rx.z);
                dx[3] = make_float2(rx.w, rx.w);
                int dd = le_h * 8;
                se[nxt][dd + 0][le_c] = re0.x; se[nxt][dd + 1][le_c] = re0.y;
                se[nxt][dd + 2][le_c] = re0.z; se[nxt][dd + 3][le_c] = re0.w;
                se[nxt][dd + 4][le_c] = re1.x; se[nxt][dd + 5][le_c] = re1.y;
                se[nxt][dd + 6][le_c] = re1.z; se[nxt][dd + 7][le_c] = re1.w;
            }
            __syncthreads();
        }

        // ---- tile epilogue: reference-emulated scores + argmin over 128 codes
        const int kb = t * NT + 8 * j;
        float cn[8];
#pragma unroll
        for (int c = 0; c < 8; c++) cn[c] = g_cnorm[kb + c];

#pragma unroll
        for (int p = 0; p < 4; p++) {
            float best = INF;
            int bk = kb;
#pragma unroll
            for (int c = 0; c < 8; c++) {
                unsigned long long a = acc[p][c >> 1];
                unsigned u = (c & 1) ? (unsigned)(a >> 32) : (unsigned)(a & 0xffffffffu);
                float dot = __uint_as_float(u);
                // s = fl(fl(A - 2*dot) + C)  -- exact reference association,
                // no fma contraction (intrinsics are never contracted).
                float tq = __fadd_rn(Ap[p], __fmul_rn(-2.0f, dot));
                float s  = __fadd_rn(tq, cn[c]);
                if (s < best) { best = s; bk = kb + c; } // ascending c => first-min
            }
            // reduce across the 16 code-groups (half-warp, width 16)
#pragma unroll
            for (int off = 8; off; off >>= 1) {
                float ov = __shfl_down_sync(0xffffffffu, best, off, 16);
                int   ok = __shfl_down_sync(0xffffffffu, bk,   off, 16);
                if (ov < best || (ov == best && ok < bk)) { best = ov; bk = ok; }
            }
            if (j == 0 && best < run_v[p]) { run_v[p] = best; run_k[p] = bk; }
        }
    }

    if (j == 0) {
#pragma unroll
        for (int p = 0; p < 4; p++) {
            g_idx[n0 + 4 * i + p] = run_k[p];
            atomicAdd(&g_count[run_k[p]], 1.0f);
        }
    }
}

// ---------------- kernel 3: dw[k][d] += flat[n][d] scatter ----------------
__global__ void k_dw(const float* __restrict__ x) {
    const int n0 = blockIdx.x * 64;
    const int b = n0 >> 10, s0 = n0 & 1023;
    const int t = threadIdx.x;
    const int p  = t & 63;
    const int dg = t >> 6;                       // 0..3
    const int kidx = g_idx[n0 + p];
    const float* xb = x + (size_t)b * XSTRIDE_B + s0 + p;
    float* dwr = g_dw + (size_t)kidx * DIM;
#pragma unroll 4
    for (int dd = 0; dd < 64; dd++) {
        int d = dg + 4 * dd;
        atomicAdd(&dwr[d], xb[(size_t)d * SPATIAL]);
    }
}

// ---------------- kernel 4: EMA update + normalized embedding ----------------
__global__ void k_ema(const float* __restrict__ cs, const float* __restrict__ eavg,
                      float* __restrict__ out) {
    const int idx = blockIdx.x * blockDim.x + threadIdx.x;   // 0..K*D-1
    const int k = idx >> 8;
    const float ncs = cs[k] * 0.99f + 0.01f * g_count[k];
    const float na  = eavg[idx] * 0.99f + 0.01f * g_dw[idx];
    out[EAVG_OFF + idx] = na;
    out[EMB_OFF + idx]  = na / fmaxf(ncs, 1e-5f);
    if ((idx & 255) == 0) out[CS_OFF + k] = ncs;
}

// ---------------- kernel 5: quantized output (x layout) + loss ----------------
__global__ void k_quant(const float* __restrict__ x, const float* __restrict__ emb,
                        float* __restrict__ out) {
    __shared__ float sq[32][257];
    __shared__ float red[8];
    const int n0 = blockIdx.x * 32;
    const int b = n0 >> 10, s0 = n0 & 1023;
    const int t = threadIdx.x;

    // phase 1: gather e rows coalesced along channel
    {
        int s  = t >> 3;            // 0..31
        int c0 = (t & 7) * 32;
        int kidx = g_idx[n0 + s];
        const float4* er = reinterpret_cast<const float4*>(emb + (size_t)kidx * DIM + c0);
#pragma unroll
        for (int q = 0; q < 8; q++) {
            float4 v = er[q];
            sq[s][c0 + 4 * q + 0] = v.x;
            sq[s][c0 + 4 * q + 1] = v.y;
            sq[s][c0 + 4 * q + 2] = v.z;
            sq[s][c0 + 4 * q + 3] = v.w;
        }
    }
    __syncthreads();

    // phase 2: write in x layout (coalesced along spatial) + accumulate loss
    const int s2 = t & 31;
    const int cg = t >> 5;          // 0..7
    const float* xr = x   + (size_t)b * XSTRIDE_B + s0 + s2;
    float*       ob = out + (size_t)b * XSTRIDE_B + s0 + s2;
    float ls = 0.f;
#pragma unroll 8
    for (int cc = 0; cc < 32; cc++) {
        int c = cg + 8 * cc;
        float q  = sq[s2][c];
        float xv = xr[(size_t)c * SPATIAL];
        // straight-through estimator, emulated: fl(x + fl(q - x))
        ob[(size_t)c * SPATIAL] = __fadd_rn(xv, __fsub_rn(q, xv));
        float d = xv - q;
        ls = fmaf(d, d, ls);
    }
#pragma unroll
    for (int off = 16; off; off >>= 1) ls += __shfl_xor_sync(0xffffffffu, ls, off);
    int lane = t & 31, w = t >> 5;
    if (lane == 0) red[w] = ls;
    __syncthreads();
    if (t == 0) {
        float tot = 0.f;
#pragma unroll
        for (int q = 0; q < 8; q++) tot += red[q];
        atomicAdd(&g_loss, tot);
    }
}

// ---------------- kernel 6: finalize loss + perplexity ----------------
__global__ void k_final(float* __restrict__ out) {
    __shared__ float red[8];
    const int t = threadIdx.x;
    float s = 0.f;
#pragma unroll
    for (int q = 0; q < 32; q++) {
        int k = t + 256 * q;
        float p = g_count[k] * (1.f / 16384.f);
        s += p * logf(p + 1e-10f);
    }
#pragma unroll
    for (int off = 16; off; off >>= 1) s += __shfl_xor_sync(0xffffffffu, s, off);
    int lane = t & 31, w = t >> 5;
    if (lane == 0) red[w] = s;
    __syncthreads();
    if (t == 0) {
        float tot = 0.f;
#pragma unroll
        for (int q = 0; q < 8; q++) tot += red[q];
        out[PPL_OFF]  = expf(-tot);
        out[LOSS_OFF] = 0.25f * g_loss * (1.f / 4194304.f);
    }
}

// ---------------- launch ----------------
extern "C" void kernel_launch(void* const* d_in, const int* in_sizes, int n_in,
                              void* d_out, int out_size) {
    const float* x    = (const float*)d_in[0];
    const float* emb  = (const float*)d_in[1];
    const float* cs   = (const float*)d_in[2];
    const float* eavg = (const float*)d_in[3];
    float* out = (float*)d_out;

    k_zero  <<<(KCODES * DIM) / 256, 256>>>();
    k_cnorm <<<(KCODES * 32) / 256, 256>>>(emb);
    k_xnorm <<<NPTS / 256, 256>>>(x);
    k_argmin<<<NPTS / MT, 256>>>(x, emb);
    k_dw    <<<NPTS / 64, 256>>>(x);
    k_ema   <<<(KCODES * DIM) / 256, 256>>>(cs, eavg, out);
    k_quant <<<NPTS / 32, 256>>>(x, emb, out);
    k_final <<<1, 256>>>(out);
}